// round 8
// baseline (speedup 1.0000x reference)
#include <cuda_runtime.h>
#include <cstdint>

// GraphAttention: out[b,t,:] = LayerNorm(node + sum_k att_k * neigh_k)
//   att_k = dot(neigh_k, node)/15, neigh_k masked (0/1).
// Inputs: node_ids i32[B*3], neighbor_ids i32[B*3*64], neighbor_mask i32[B*3*64],
//         emb f32[500000*128], gamma f32[128], beta f32[128]. Output f32[B*3*128].

#define DDIM  128
#define KNB   64
#define NWARP 4
#define KPW   (KNB / NWARP)   // 16 neighbors per warp

__global__ __launch_bounds__(128, 8)
void ga_kernel(const int* __restrict__ node_ids,
               const int* __restrict__ nbr_ids,
               const int* __restrict__ nbr_mask,
               const float* __restrict__ emb,
               const float* __restrict__ gamma,
               const float* __restrict__ beta,
               float* __restrict__ out,
               int n_rows)
{
    const int bt = blockIdx.x;
    if (bt >= n_rows) return;

    const int tid = threadIdx.x;
    const int w   = tid >> 5;
    const int l   = tid & 31;
    const int g   = l >> 4;      // 16-lane group (0/1): which row of each pair
    const int j   = l & 15;      // lane within group: owns dims {4j..4j+3, 64+4j..64+4j+3}

    __shared__ float sacc[NWARP][DDIM];
    __shared__ float sred[2 * NWARP];
    __shared__ int   slist[NWARP][KPW];

    // Node row chunks for this lane's dims.
    const size_t nid = (size_t)node_ids[bt];
    const float4* nrow = reinterpret_cast<const float4*>(emb + nid * DDIM);
    const float4 na = nrow[j];        // dims [4j, 4j+4)
    const float4 nb = nrow[16 + j];   // dims [64+4j, 64+4j+4)

    const int* kid = nbr_ids  + (size_t)bt * KNB + w * KPW;
    const int* km  = nbr_mask + (size_t)bt * KNB + w * KPW;

    // ---- Warp compaction of unmasked neighbor ids into a dense smem list ----
    int myid = 0, mym = 0;
    if (l < KPW) { mym = __ldg(km + l); myid = __ldg(kid + l); }
    const unsigned bal = __ballot_sync(0xffffffffu, mym != 0);
    const int cnt = __popc(bal);
    const int pos = __popc(bal & ((1u << l) - 1u));
    if (mym) slist[w][pos] = myid;
    // Pad remainder with the node id: valid prefetch addresses, L2-hot rows
    // for padded loads, weight forced to 0 later.
    if (l >= cnt && l < KPW) slist[w][l] = (int)nid;
    __syncwarp();

    // ---- Fire-and-forget L2 prefetch of all 16 rows (2 instrs, 64 lines) ----
    {
        const int pr = l >> 2;
        const int po = (l & 3) * 32;              // 32 floats = 128 B line
        const float* pa0 = emb + (size_t)slist[w][pr]     * DDIM + po;
        const float* pa1 = emb + (size_t)slist[w][8 + pr] * DDIM + po;
        asm volatile("prefetch.global.L2 [%0];" :: "l"(pa0));
        asm volatile("prefetch.global.L2 [%0];" :: "l"(pa1));
    }

    // Group g processes rows {2t+g}; pairs t < tmax cover rows [0, cnt) (+<=1 pad).
    const int tmax = (cnt + 1) >> 1;

    float4 aa = make_float4(0.f, 0.f, 0.f, 0.f);   // dims [4j, 4j+4)
    float4 ab = make_float4(0.f, 0.f, 0.f, 0.f);   // dims [64+4j, 64+4j+4)

    #define ROWP(r) (reinterpret_cast<const float4*>(emb + (size_t)slist[w][(r)] * DDIM))

    // Two-pair-deep pipeline: 4 rows (2 pairs x 2 LDG.128/lane) in flight.
    float4 va, vb, ua, ub;
    if (tmax > 0) { const float4* p = ROWP(g);     va = p[j]; vb = p[16 + j]; }
    if (tmax > 1) { const float4* p = ROWP(2 + g); ua = p[j]; ub = p[16 + j]; }

    for (int t = 0; t < tmax; t++) {
        // Issue pair t+2's loads before reducing pair t.
        float4 wa, wb;
        const bool more = (t + 2 < tmax);
        if (more) {
            const float4* p = ROWP(2 * (t + 2) + g);
            wa = p[j]; wb = p[16 + j];
        }

        // Partial dot over this lane's 8 dims; 4-level reduce within the
        // 16-lane group — one chain serves both rows of the pair.
        float pd = na.x*va.x + na.y*va.y + na.z*va.z + na.w*va.w
                 + nb.x*vb.x + nb.y*vb.y + nb.z*vb.z + nb.w*vb.w;
        pd += __shfl_xor_sync(0xffffffffu, pd, 1);
        pd += __shfl_xor_sync(0xffffffffu, pd, 2);
        pd += __shfl_xor_sync(0xffffffffu, pd, 4);
        pd += __shfl_xor_sync(0xffffffffu, pd, 8);

        const int r = 2 * t + g;
        const float att = (r < cnt) ? pd * (1.0f / 15.0f) : 0.f;

        aa.x = fmaf(att, va.x, aa.x);
        aa.y = fmaf(att, va.y, aa.y);
        aa.z = fmaf(att, va.z, aa.z);
        aa.w = fmaf(att, va.w, aa.w);
        ab.x = fmaf(att, vb.x, ab.x);
        ab.y = fmaf(att, vb.y, ab.y);
        ab.z = fmaf(att, vb.z, ab.z);
        ab.w = fmaf(att, vb.w, ab.w);

        va = ua; vb = ub;
        if (more) { ua = wa; ub = wb; }
    }
    #undef ROWP

    // Cross-group combine (once): same dims live in lane l and lane l^16.
    aa.x += __shfl_xor_sync(0xffffffffu, aa.x, 16);
    aa.y += __shfl_xor_sync(0xffffffffu, aa.y, 16);
    aa.z += __shfl_xor_sync(0xffffffffu, aa.z, 16);
    aa.w += __shfl_xor_sync(0xffffffffu, aa.w, 16);
    ab.x += __shfl_xor_sync(0xffffffffu, ab.x, 16);
    ab.y += __shfl_xor_sync(0xffffffffu, ab.y, 16);
    ab.z += __shfl_xor_sync(0xffffffffu, ab.z, 16);
    ab.w += __shfl_xor_sync(0xffffffffu, ab.w, 16);

    if (g == 0) {
        float4* s4 = reinterpret_cast<float4*>(&sacc[w][0]);
        s4[j]      = aa;
        s4[16 + j] = ab;
    }
    __syncthreads();

    // Thread tid owns dim d = tid.
    const int d = tid;
    const float nd = __ldg(emb + nid * DDIM + d);   // L1/L2 hit (row already fetched)
    float x = nd + sacc[0][d] + sacc[1][d] + sacc[2][d] + sacc[3][d];

    // Block-level LayerNorm reduction over 128 values
    float s = x, s2 = x * x;
    #pragma unroll
    for (int off = 16; off > 0; off >>= 1) {
        s  += __shfl_xor_sync(0xffffffffu, s,  off);
        s2 += __shfl_xor_sync(0xffffffffu, s2, off);
    }
    if (l == 0) { sred[w] = s; sred[NWARP + w] = s2; }
    __syncthreads();

    const float ss  = sred[0] + sred[1] + sred[2] + sred[3];
    const float ss2 = sred[NWARP + 0] + sred[NWARP + 1] + sred[NWARP + 2] + sred[NWARP + 3];

    const float mu  = ss * (1.0f / DDIM);
    const float var = ss2 * (1.0f / DDIM) - mu * mu;
    const float inv = rsqrtf(var + 1e-5f);

    out[(size_t)bt * DDIM + d] = (x - mu) * inv * gamma[d] + beta[d];
}

extern "C" void kernel_launch(void* const* d_in, const int* in_sizes, int n_in,
                              void* d_out, int out_size)
{
    const int*   node_ids = (const int*)  d_in[0];
    const int*   nbr_ids  = (const int*)  d_in[1];
    const int*   nbr_mask = (const int*)  d_in[2];
    const float* emb      = (const float*)d_in[3];
    const float* gamma    = (const float*)d_in[4];
    const float* beta     = (const float*)d_in[5];
    float*       out      = (float*)d_out;

    const int n_rows = in_sizes[0];          // B*3 = 12288
    ga_kernel<<<n_rows, 128>>>(node_ids, nbr_ids, nbr_mask, emb, gamma, beta,
                               out, n_rows);
}

// round 9
// speedup vs baseline: 1.0960x; 1.0960x over previous
#include <cuda_runtime.h>
#include <cstdint>

// GraphAttention: out[b,t,:] = LayerNorm(node + sum_k att_k * neigh_k)
//   att_k = dot(neigh_k, node)/15, neigh_k masked (0/1).
// Inputs: node_ids i32[B*3], neighbor_ids i32[B*3*64], neighbor_mask i32[B*3*64],
//         emb f32[500000*128], gamma f32[128], beta f32[128]. Output f32[B*3*128].
//
// R9 = R5 (best: 41.2us) with occupancy target 8 -> 10. Single-variable change.

#define DDIM  128
#define KNB   64
#define NWARP 4
#define KPW   (KNB / NWARP)   // 16 neighbors per warp

__global__ __launch_bounds__(128, 10)
void ga_kernel(const int* __restrict__ node_ids,
               const int* __restrict__ nbr_ids,
               const int* __restrict__ nbr_mask,
               const float* __restrict__ emb,
               const float* __restrict__ gamma,
               const float* __restrict__ beta,
               float* __restrict__ out,
               int n_rows)
{
    const int bt = blockIdx.x;
    if (bt >= n_rows) return;

    const int tid = threadIdx.x;
    const int w   = tid >> 5;
    const int l   = tid & 31;

    __shared__ float sacc[NWARP][DDIM];
    __shared__ float sred[2 * NWARP];
    __shared__ int   slist[NWARP][KPW];

    // Node row: lane l holds dims [4l, 4l+4)
    const size_t nid = (size_t)node_ids[bt];
    const float4 n4 = reinterpret_cast<const float4*>(emb + nid * DDIM)[l];

    const int* kid = nbr_ids  + (size_t)bt * KNB + w * KPW;
    const int* km  = nbr_mask + (size_t)bt * KNB + w * KPW;

    // ---- Warp compaction of unmasked neighbor ids into a dense smem list ----
    int myid = 0, mym = 0;
    if (l < KPW) { mym = __ldg(km + l); myid = __ldg(kid + l); }
    const unsigned bal = __ballot_sync(0xffffffffu, mym != 0);
    const int cnt = __popc(bal);
    const int pos = __popc(bal & ((1u << l) - 1u));
    if (mym) slist[w][pos] = myid;
    // Pad the ENTIRE remainder with the node id: valid addresses for prefetch,
    // L2-hot rows for the padded LDGs, weight forced to 0 later.
    if (l >= cnt && l < KPW) slist[w][l] = (int)nid;
    __syncwarp();

    // ---- Fire-and-forget L2 prefetch of all 16 rows (2 instrs, 64 lines) ----
    // Lane l prefetches 128B line (l&3) of row (l>>2) and row 8+(l>>2).
    {
        const int pr = l >> 2;
        const int po = (l & 3) * 32;              // 32 floats = 128 B
        const float* pa0 = emb + (size_t)slist[w][pr]     * DDIM + po;
        const float* pa1 = emb + (size_t)slist[w][8 + pr] * DDIM + po;
        asm volatile("prefetch.global.L2 [%0];" :: "l"(pa0));
        asm volatile("prefetch.global.L2 [%0];" :: "l"(pa1));
    }

    float4 acc = make_float4(0.f, 0.f, 0.f, 0.f);
    const int cnt_pad = (cnt + 3) & ~3;
    const int groups  = cnt_pad >> 2;

    #define ROW(j) (reinterpret_cast<const float4*>(emb + (size_t)slist[w][(j)] * DDIM)[l])

    float4 v0, v1, v2, v3;
    if (groups > 0) {
        v0 = ROW(0); v1 = ROW(1); v2 = ROW(2); v3 = ROW(3);
    }

    for (int g = 0; g < groups; g++) {
        // Issue next group's 4 independent row loads before touching this group.
        float4 u0 = v0, u1 = v1, u2 = v2, u3 = v3;
        if (g + 1 < groups) {
            const int j = 4 * (g + 1);
            u0 = ROW(j + 0); u1 = ROW(j + 1); u2 = ROW(j + 2); u3 = ROW(j + 3);
        }

        // 4 independent dot products -> 4 interleaved butterfly chains.
        float p0 = n4.x*v0.x + n4.y*v0.y + n4.z*v0.z + n4.w*v0.w;
        float p1 = n4.x*v1.x + n4.y*v1.y + n4.z*v1.z + n4.w*v1.w;
        float p2 = n4.x*v2.x + n4.y*v2.y + n4.z*v2.z + n4.w*v2.w;
        float p3 = n4.x*v3.x + n4.y*v3.y + n4.z*v3.z + n4.w*v3.w;
        #pragma unroll
        for (int off = 16; off > 0; off >>= 1) {
            p0 += __shfl_xor_sync(0xffffffffu, p0, off);
            p1 += __shfl_xor_sync(0xffffffffu, p1, off);
            p2 += __shfl_xor_sync(0xffffffffu, p2, off);
            p3 += __shfl_xor_sync(0xffffffffu, p3, off);
        }
        const int jb = 4 * g;
        const float a0 = (jb + 0 < cnt) ? p0 * (1.0f / 15.0f) : 0.f;
        const float a1 = (jb + 1 < cnt) ? p1 * (1.0f / 15.0f) : 0.f;
        const float a2 = (jb + 2 < cnt) ? p2 * (1.0f / 15.0f) : 0.f;
        const float a3 = (jb + 3 < cnt) ? p3 * (1.0f / 15.0f) : 0.f;

        acc.x = fmaf(a0, v0.x, fmaf(a1, v1.x, fmaf(a2, v2.x, fmaf(a3, v3.x, acc.x))));
        acc.y = fmaf(a0, v0.y, fmaf(a1, v1.y, fmaf(a2, v2.y, fmaf(a3, v3.y, acc.y))));
        acc.z = fmaf(a0, v0.z, fmaf(a1, v1.z, fmaf(a2, v2.z, fmaf(a3, v3.z, acc.z))));
        acc.w = fmaf(a0, v0.w, fmaf(a1, v1.w, fmaf(a2, v2.w, fmaf(a3, v3.w, acc.w))));

        v0 = u0; v1 = u1; v2 = u2; v3 = u3;
    }
    #undef ROW

    reinterpret_cast<float4*>(&sacc[w][0])[l] = acc;
    __syncthreads();

    // Thread tid owns dim d = tid.
    const int d = tid;
    const float nd = __ldg(emb + nid * DDIM + d);   // L1/L2 hit (row already fetched)
    float x = nd + sacc[0][d] + sacc[1][d] + sacc[2][d] + sacc[3][d];

    // Block-level LayerNorm reduction over 128 values
    float s = x, s2 = x * x;
    #pragma unroll
    for (int off = 16; off > 0; off >>= 1) {
        s  += __shfl_xor_sync(0xffffffffu, s,  off);
        s2 += __shfl_xor_sync(0xffffffffu, s2, off);
    }
    if (l == 0) { sred[w] = s; sred[NWARP + w] = s2; }
    __syncthreads();

    const float ss  = sred[0] + sred[1] + sred[2] + sred[3];
    const float ss2 = sred[NWARP + 0] + sred[NWARP + 1] + sred[NWARP + 2] + sred[NWARP + 3];

    const float mu  = ss * (1.0f / DDIM);
    const float var = ss2 * (1.0f / DDIM) - mu * mu;
    const float inv = rsqrtf(var + 1e-5f);

    out[(size_t)bt * DDIM + d] = (x - mu) * inv * gamma[d] + beta[d];
}

extern "C" void kernel_launch(void* const* d_in, const int* in_sizes, int n_in,
                              void* d_out, int out_size)
{
    const int*   node_ids = (const int*)  d_in[0];
    const int*   nbr_ids  = (const int*)  d_in[1];
    const int*   nbr_mask = (const int*)  d_in[2];
    const float* emb      = (const float*)d_in[3];
    const float* gamma    = (const float*)d_in[4];
    const float* beta     = (const float*)d_in[5];
    float*       out      = (float*)d_out;

    const int n_rows = in_sizes[0];          // B*3 = 12288
    ga_kernel<<<n_rows, 128>>>(node_ids, nbr_ids, nbr_mask, emb, gamma, beta,
                               out, n_rows);
}

// round 10
// speedup vs baseline: 1.1508x; 1.0500x over previous
#include <cuda_runtime.h>
#include <cstdint>

// GraphAttention: out[b,t,:] = LayerNorm(node + sum_k att_k * neigh_k)
//   att_k = dot(neigh_k, node)/15, neigh_k masked (0/1).
// Inputs: node_ids i32[B*3], neighbor_ids i32[B*3*64], neighbor_mask i32[B*3*64],
//         emb f32[500000*128], gamma f32[128], beta f32[128]. Output f32[B*3*128].
//
// R10 = R5 (best: 41.2us) with per-line prefetch.global.L2 (64 wavefronts/warp)
// replaced by 16x cp.async.bulk.prefetch.L2 (512B each, bulk/TMA path, no L1tex).

#define DDIM  128
#define KNB   64
#define NWARP 4
#define KPW   (KNB / NWARP)   // 16 neighbors per warp

__global__ __launch_bounds__(128, 8)
void ga_kernel(const int* __restrict__ node_ids,
               const int* __restrict__ nbr_ids,
               const int* __restrict__ nbr_mask,
               const float* __restrict__ emb,
               const float* __restrict__ gamma,
               const float* __restrict__ beta,
               float* __restrict__ out,
               int n_rows)
{
    const int bt = blockIdx.x;
    if (bt >= n_rows) return;

    const int tid = threadIdx.x;
    const int w   = tid >> 5;
    const int l   = tid & 31;

    __shared__ float sacc[NWARP][DDIM];
    __shared__ float sred[2 * NWARP];
    __shared__ int   slist[NWARP][KPW];

    // Node row: lane l holds dims [4l, 4l+4)
    const size_t nid = (size_t)node_ids[bt];
    const float4 n4 = reinterpret_cast<const float4*>(emb + nid * DDIM)[l];

    const int* kid = nbr_ids  + (size_t)bt * KNB + w * KPW;
    const int* km  = nbr_mask + (size_t)bt * KNB + w * KPW;

    // ---- Warp compaction of unmasked neighbor ids into a dense smem list ----
    int myid = 0, mym = 0;
    if (l < KPW) { mym = __ldg(km + l); myid = __ldg(kid + l); }
    const unsigned bal = __ballot_sync(0xffffffffu, mym != 0);
    const int cnt = __popc(bal);
    const int pos = __popc(bal & ((1u << l) - 1u));
    if (mym) slist[w][pos] = myid;
    // Pad the ENTIRE remainder with the node id: valid addresses for prefetch,
    // L2-hot rows for the padded LDGs, weight forced to 0 later.
    if (l >= cnt && l < KPW) slist[w][l] = (int)nid;
    __syncwarp();

    // ---- Bulk L2 prefetch: lane l (l<16) prefetches its whole 512B row via the
    // bulk/TMA path — 16 ops/warp, zero L1tex wavefronts. Only rows that will
    // actually be loaded (incl. <=3 pad rows which are L2-hot node rows).
    if (l < KPW) {
        const float* pa = emb + (size_t)slist[w][l] * DDIM;
        asm volatile("cp.async.bulk.prefetch.L2.global [%0], %1;"
                     :: "l"(pa), "r"(512));
    }

    float4 acc = make_float4(0.f, 0.f, 0.f, 0.f);
    const int cnt_pad = (cnt + 3) & ~3;
    const int groups  = cnt_pad >> 2;

    #define ROW(j) (reinterpret_cast<const float4*>(emb + (size_t)slist[w][(j)] * DDIM)[l])

    float4 v0, v1, v2, v3;
    if (groups > 0) {
        v0 = ROW(0); v1 = ROW(1); v2 = ROW(2); v3 = ROW(3);
    }

    for (int g = 0; g < groups; g++) {
        // Issue next group's 4 independent row loads before touching this group.
        float4 u0 = v0, u1 = v1, u2 = v2, u3 = v3;
        if (g + 1 < groups) {
            const int j = 4 * (g + 1);
            u0 = ROW(j + 0); u1 = ROW(j + 1); u2 = ROW(j + 2); u3 = ROW(j + 3);
        }

        // 4 independent dot products -> 4 interleaved butterfly chains.
        float p0 = n4.x*v0.x + n4.y*v0.y + n4.z*v0.z + n4.w*v0.w;
        float p1 = n4.x*v1.x + n4.y*v1.y + n4.z*v1.z + n4.w*v1.w;
        float p2 = n4.x*v2.x + n4.y*v2.y + n4.z*v2.z + n4.w*v2.w;
        float p3 = n4.x*v3.x + n4.y*v3.y + n4.z*v3.z + n4.w*v3.w;
        #pragma unroll
        for (int off = 16; off > 0; off >>= 1) {
            p0 += __shfl_xor_sync(0xffffffffu, p0, off);
            p1 += __shfl_xor_sync(0xffffffffu, p1, off);
            p2 += __shfl_xor_sync(0xffffffffu, p2, off);
            p3 += __shfl_xor_sync(0xffffffffu, p3, off);
        }
        const int jb = 4 * g;
        const float a0 = (jb + 0 < cnt) ? p0 * (1.0f / 15.0f) : 0.f;
        const float a1 = (jb + 1 < cnt) ? p1 * (1.0f / 15.0f) : 0.f;
        const float a2 = (jb + 2 < cnt) ? p2 * (1.0f / 15.0f) : 0.f;
        const float a3 = (jb + 3 < cnt) ? p3 * (1.0f / 15.0f) : 0.f;

        acc.x = fmaf(a0, v0.x, fmaf(a1, v1.x, fmaf(a2, v2.x, fmaf(a3, v3.x, acc.x))));
        acc.y = fmaf(a0, v0.y, fmaf(a1, v1.y, fmaf(a2, v2.y, fmaf(a3, v3.y, acc.y))));
        acc.z = fmaf(a0, v0.z, fmaf(a1, v1.z, fmaf(a2, v2.z, fmaf(a3, v3.z, acc.z))));
        acc.w = fmaf(a0, v0.w, fmaf(a1, v1.w, fmaf(a2, v2.w, fmaf(a3, v3.w, acc.w))));

        v0 = u0; v1 = u1; v2 = u2; v3 = u3;
    }
    #undef ROW

    reinterpret_cast<float4*>(&sacc[w][0])[l] = acc;
    __syncthreads();

    // Thread tid owns dim d = tid.
    const int d = tid;
    const float nd = __ldg(emb + nid * DDIM + d);   // L1/L2 hit (row already fetched)
    float x = nd + sacc[0][d] + sacc[1][d] + sacc[2][d] + sacc[3][d];

    // Block-level LayerNorm reduction over 128 values
    float s = x, s2 = x * x;
    #pragma unroll
    for (int off = 16; off > 0; off >>= 1) {
        s  += __shfl_xor_sync(0xffffffffu, s,  off);
        s2 += __shfl_xor_sync(0xffffffffu, s2, off);
    }
    if (l == 0) { sred[w] = s; sred[NWARP + w] = s2; }
    __syncthreads();

    const float ss  = sred[0] + sred[1] + sred[2] + sred[3];
    const float ss2 = sred[NWARP + 0] + sred[NWARP + 1] + sred[NWARP + 2] + sred[NWARP + 3];

    const float mu  = ss * (1.0f / DDIM);
    const float var = ss2 * (1.0f / DDIM) - mu * mu;
    const float inv = rsqrtf(var + 1e-5f);

    out[(size_t)bt * DDIM + d] = (x - mu) * inv * gamma[d] + beta[d];
}

extern "C" void kernel_launch(void* const* d_in, const int* in_sizes, int n_in,
                              void* d_out, int out_size)
{
    const int*   node_ids = (const int*)  d_in[0];
    const int*   nbr_ids  = (const int*)  d_in[1];
    const int*   nbr_mask = (const int*)  d_in[2];
    const float* emb      = (const float*)d_in[3];
    const float* gamma    = (const float*)d_in[4];
    const float* beta     = (const float*)d_in[5];
    float*       out      = (float*)d_out;

    const int n_rows = in_sizes[0];          // B*3 = 12288
    ga_kernel<<<n_rows, 128>>>(node_ids, nbr_ids, nbr_mask, emb, gamma, beta,
                               out, n_rows);
}